// round 10
// baseline (speedup 1.0000x reference)
#include <cuda_runtime.h>
#include <cuda_bf16.h>
#include <mma.h>

using namespace nvcuda;

#define N_NODES 20000
#define N_PAD   20096
#define E_EDGES 640000
#define E_TOT   (E_EDGES + N_NODES)
#define IN_F    256
#define HEADS   8
#define HF      64
#define OUTF    32
#define NEG_SLOPE 0.2f
#define MAXDEG  128

// ------------------- scratch -------------------
__device__ __nv_bfloat16  g_h1b[(size_t)N_PAD * HEADS * HF];
__device__ float          g_h1m[(size_t)N_PAD * HF];
__device__ __nv_bfloat16  g_h2b[(size_t)N_PAD * HEADS * OUTF];
__device__ float g_as1[N_PAD * HEADS];
__device__ float g_ad1[N_PAD * HEADS];
__device__ float g_as2[N_PAD * HEADS];
__device__ float g_ad2[N_PAD * HEADS];
__device__ int   g_cnt[N_NODES];
__device__ int   g_csr[(size_t)N_NODES * MAXDEG];

// ------------------- padded-bucket CSR build -------------------
__global__ void scatter_kernel(const int* __restrict__ src, const int* __restrict__ dst,
                               int* __restrict__ cnt, int* __restrict__ csr) {
    int i = blockIdx.x * blockDim.x + threadIdx.x;
    if (i >= E_TOT) return;
    int s, d;
    if (i < E_EDGES) { s = src[i]; d = dst[i]; }
    else             { s = d = i - E_EDGES; }
    int p = atomicAdd(&cnt[d], 1);
    int slot = (p < MAXDEG) ? d * MAXDEG + p : d * MAXDEG;
    csr[slot] = s;
}

// ------------------- TF32 GEMM + fused logits/bf16 epilogue -------------------
template<int GUARD_A, int CH>
__global__ __launch_bounds__(256, 2)
void gemm_fused_kernel(const float* __restrict__ A, const float* __restrict__ B,
                       __nv_bfloat16* __restrict__ hb,
                       const float* __restrict__ att_src, const float* __restrict__ att_dst,
                       float* __restrict__ asrc, float* __restrict__ adst,
                       int M, int Nn, int K) {
    __shared__ float As[2][128][36];
    __shared__ float Bs[2][32][68];

    const int bm = blockIdx.y * 128;
    const int bn = blockIdx.x * 64;
    const int t = threadIdx.x;
    const int wid = t >> 5;
    const int lane = t & 31;
    const int wm = (wid & 3) * 32;
    const int wn = (wid >> 2) * 32;

    const int ar0 = (t * 4) >> 5;
    const int ac  = (t * 4) & 31;
    const int br0 = (t * 4) >> 6;
    const int bc  = (t * 4) & 63;

    wmma::fragment<wmma::accumulator, 16, 16, 8, float> c[2][2];
    #pragma unroll
    for (int i = 0; i < 2; i++)
        #pragma unroll
        for (int j = 0; j < 2; j++)
            wmma::fill_fragment(c[i][j], 0.0f);

    const int nk = K / 32;

    float4 aR[4], bR[2];
    #pragma unroll
    for (int i = 0; i < 4; i++) {
        int r = ar0 + i * 32;
        if (!GUARD_A || (bm + r) < M)
            aR[i] = *(const float4*)(A + (size_t)(bm + r) * K + ac);
        else
            aR[i] = make_float4(0.f, 0.f, 0.f, 0.f);
    }
    #pragma unroll
    for (int i = 0; i < 2; i++)
        bR[i] = *(const float4*)(B + (size_t)(br0 + i * 16) * Nn + bn + bc);

    #pragma unroll
    for (int i = 0; i < 4; i++) {
        float4 v = aR[i];
        v.x = wmma::__float_to_tf32(v.x); v.y = wmma::__float_to_tf32(v.y);
        v.z = wmma::__float_to_tf32(v.z); v.w = wmma::__float_to_tf32(v.w);
        *(float4*)&As[0][ar0 + i * 32][ac] = v;
    }
    #pragma unroll
    for (int i = 0; i < 2; i++) {
        float4 v = bR[i];
        v.x = wmma::__float_to_tf32(v.x); v.y = wmma::__float_to_tf32(v.y);
        v.z = wmma::__float_to_tf32(v.z); v.w = wmma::__float_to_tf32(v.w);
        *(float4*)&Bs[0][br0 + i * 16][bc] = v;
    }
    __syncthreads();

    for (int kt = 0; kt < nk; kt++) {
        const int cur = kt & 1;
        const int nxt = cur ^ 1;

        if (kt + 1 < nk) {
            int k0 = (kt + 1) * 32;
            #pragma unroll
            for (int i = 0; i < 4; i++) {
                int r = ar0 + i * 32;
                if (!GUARD_A || (bm + r) < M)
                    aR[i] = *(const float4*)(A + (size_t)(bm + r) * K + k0 + ac);
                else
                    aR[i] = make_float4(0.f, 0.f, 0.f, 0.f);
            }
            #pragma unroll
            for (int i = 0; i < 2; i++)
                bR[i] = *(const float4*)(B + (size_t)(k0 + br0 + i * 16) * Nn + bn + bc);
        }

        #pragma unroll
        for (int kk = 0; kk < 4; kk++) {
            wmma::fragment<wmma::matrix_a, 16, 16, 8, wmma::precision::tf32, wmma::row_major> a[2];
            wmma::fragment<wmma::matrix_b, 16, 16, 8, wmma::precision::tf32, wmma::row_major> b[2];
            #pragma unroll
            for (int i = 0; i < 2; i++)
                wmma::load_matrix_sync(a[i], &As[cur][wm + i * 16][kk * 8], 36);
            #pragma unroll
            for (int j = 0; j < 2; j++)
                wmma::load_matrix_sync(b[j], &Bs[cur][kk * 8][wn + j * 16], 68);
            #pragma unroll
            for (int i = 0; i < 2; i++)
                #pragma unroll
                for (int j = 0; j < 2; j++)
                    wmma::mma_sync(c[i][j], a[i], b[j], c[i][j]);
        }

        if (kt + 1 < nk) {
            #pragma unroll
            for (int i = 0; i < 4; i++) {
                float4 v = aR[i];
                v.x = wmma::__float_to_tf32(v.x); v.y = wmma::__float_to_tf32(v.y);
                v.z = wmma::__float_to_tf32(v.z); v.w = wmma::__float_to_tf32(v.w);
                *(float4*)&As[nxt][ar0 + i * 32][ac] = v;
            }
            #pragma unroll
            for (int i = 0; i < 2; i++) {
                float4 v = bR[i];
                v.x = wmma::__float_to_tf32(v.x); v.y = wmma::__float_to_tf32(v.y);
                v.z = wmma::__float_to_tf32(v.z); v.w = wmma::__float_to_tf32(v.w);
                *(float4*)&Bs[nxt][br0 + i * 16][bc] = v;
            }
        }
        __syncthreads();
    }

    float (*Cs)[68] = reinterpret_cast<float(*)[68]>(&As[0][0][0]);
    #pragma unroll
    for (int i = 0; i < 2; i++)
        #pragma unroll
        for (int j = 0; j < 2; j++)
            wmma::store_matrix_sync(&Cs[wm + i * 16][wn + j * 16], c[i][j], 68,
                                    wmma::mem_row_major);
    __syncthreads();

    const float a_s0 = __ldg(att_src + bn + lane * 2);
    const float a_s1 = __ldg(att_src + bn + lane * 2 + 1);
    const float a_d0 = __ldg(att_dst + bn + lane * 2);
    const float a_d1 = __ldg(att_dst + bn + lane * 2 + 1);

    #pragma unroll
    for (int rr = 0; rr < 16; rr++) {
        int r = wid * 16 + rr;
        float2 v = *(const float2*)&Cs[r][lane * 2];
        ((__nv_bfloat162*)(hb + (size_t)(bm + r) * Nn + bn))[lane] =
            __floats2bfloat162_rn(v.x, v.y);
        float s1 = v.x * a_s0 + v.y * a_s1;
        float s2 = v.x * a_d0 + v.y * a_d1;
        if (CH == 64) {
            #pragma unroll
            for (int o = 16; o > 0; o >>= 1) {
                s1 += __shfl_xor_sync(0xffffffffu, s1, o);
                s2 += __shfl_xor_sync(0xffffffffu, s2, o);
            }
            if (lane == 0) {
                int head = bn >> 6;
                asrc[(bm + r) * HEADS + head] = s1;
                adst[(bm + r) * HEADS + head] = s2;
            }
        } else {
            #pragma unroll
            for (int o = 8; o > 0; o >>= 1) {
                s1 += __shfl_xor_sync(0xffffffffu, s1, o);
                s2 += __shfl_xor_sync(0xffffffffu, s2, o);
            }
            if ((lane & 15) == 0) {
                int head = (bn >> 5) + (lane >> 4);
                asrc[(bm + r) * HEADS + head] = s1;
                adst[(bm + r) * HEADS + head] = s2;
            }
        }
    }
}

// ------------------- fused GAT aggregation ------------------------
// Weight computed inline: wj = exp(leaky(asrc[s][h] + adst[node][h])).
// Each warp covers ALL 8 heads of one edge: lane -> head = lane>>2,
// channels cbase = (lane&3) * (C/4). 8 warps = 8 edge chunks.
// Accumulation via packed fma.rn.f32x2 (FFMA2); bf16->f32 by shift/mask.
template <int C, bool RELU>
__global__ __launch_bounds__(256)
void aggregate_kernel(const __nv_bfloat16* __restrict__ h,
                      const float* __restrict__ asrc, const float* __restrict__ adst,
                      const int* __restrict__ cnt, const int* __restrict__ csr,
                      const float* __restrict__ bias, float* __restrict__ out) {
    constexpr int NQ = 8;
    constexpr int CV = C / 4;           // channels per lane: 16 (C=64) / 8 (C=32)
    constexpr int NACC = CV / 2;        // packed accumulators: 8 / 4
    const int node = blockIdx.x;
    const int wid = threadIdx.x >> 5;
    const int lane = threadIdx.x & 31;
    const int q = wid;
    const int head = lane >> 2;
    const int cbase = (lane & 3) * CV;

    const int len = min(cnt[node], MAXDEG);
    const int chunk = (len + NQ - 1) / NQ;
    const int lo = node * MAXDEG + min(len, q * chunk);
    const int hi = node * MAXDEG + min(len, q * chunk + chunk);

    const float ad = __ldg(&adst[node * HEADS + head]);

    const unsigned rowBytes = (unsigned)(C * HEADS * 2);   // 1024 / 512
    const unsigned laneOff  = (unsigned)(head * C + cbase) * 2u;
    const char* hbase = (const char*)h;

    float den = 0.f;
    unsigned long long acc2[NACC];
    #pragma unroll
    for (int v = 0; v < NACC; v++) acc2[v] = 0ULL;

    for (int j = lo; j < hi; j++) {
        int s = __ldg(&csr[j]);
        float e = __ldg(&asrc[s * HEADS + head]) + ad;
        e = (e >= 0.f) ? e : NEG_SLOPE * e;
        float wj = __expf(e);
        den += wj;
        unsigned long long wj2;
        asm("mov.b64 %0, {%1, %1};" : "=l"(wj2) : "f"(wj));
        unsigned off = (unsigned)s * rowBytes + laneOff;
        uint4 r0 = __ldg((const uint4*)(hbase + off));
        unsigned raws[CV / 2 > 4 ? 8 : 4];
        raws[0] = r0.x; raws[1] = r0.y; raws[2] = r0.z; raws[3] = r0.w;
        if (CV == 16) {
            uint4 r1 = __ldg((const uint4*)(hbase + off + 16));
            raws[4] = r1.x; raws[5] = r1.y; raws[6] = r1.z; raws[7] = r1.w;
        }
        #pragma unroll
        for (int k = 0; k < NACC; k++) {
            unsigned lo32 = raws[k] << 16;
            unsigned hi32 = raws[k] & 0xffff0000u;
            unsigned long long hv;
            asm("mov.b64 %0, {%1, %2};" : "=l"(hv) : "r"(lo32), "r"(hi32));
            asm("fma.rn.f32x2 %0, %1, %2, %0;" : "+l"(acc2[k]) : "l"(hv), "l"(wj2));
        }
    }

    __shared__ float sacc[NQ][HEADS][C];
    __shared__ float sden[NQ][HEADS];
    #pragma unroll
    for (int k = 0; k < NACC; k++) {
        float a0, a1;
        asm("mov.b64 {%0, %1}, %2;" : "=f"(a0), "=f"(a1) : "l"(acc2[k]));
        sacc[q][head][cbase + 2 * k]     = a0;
        sacc[q][head][cbase + 2 * k + 1] = a1;
    }
    if ((lane & 3) == 0) sden[q][head] = den;
    __syncthreads();

    if (threadIdx.x < C) {
        int cc = threadIdx.x;
        float sum = 0.f;
        #pragma unroll
        for (int hh = 0; hh < HEADS; hh++) {
            float a = 0.f, d = 0.f;
            #pragma unroll
            for (int qq = 0; qq < NQ; qq++) {
                a += sacc[qq][hh][cc];
                d += sden[qq][hh];
            }
            sum += a / d;
        }
        sum = sum * (1.0f / HEADS) + bias[cc];
        if (RELU) sum = fmaxf(sum, 0.f);
        out[(size_t)node * C + cc] = sum;
    }
}

// ------------------- launch -------------------
extern "C" void kernel_launch(void* const* d_in, const int* in_sizes, int n_in,
                              void* d_out, int out_size) {
    const float* x        = (const float*)d_in[0];
    const int*   ei       = (const int*)  d_in[1];
    const float* W1       = (const float*)d_in[2];
    const float* att_src1 = (const float*)d_in[3];
    const float* att_dst1 = (const float*)d_in[4];
    const float* b1       = (const float*)d_in[5];
    const float* W2       = (const float*)d_in[6];
    const float* att_src2 = (const float*)d_in[7];
    const float* att_dst2 = (const float*)d_in[8];
    const float* b2       = (const float*)d_in[9];
    float* out = (float*)d_out;

    const int* src = ei;
    const int* dst = ei + E_EDGES;

    float *h1m, *as1, *ad1, *as2, *ad2;
    __nv_bfloat16 *h1b, *h2b;
    int *cnt, *csr;
    cudaGetSymbolAddress((void**)&h1b,  g_h1b);
    cudaGetSymbolAddress((void**)&h1m,  g_h1m);
    cudaGetSymbolAddress((void**)&h2b,  g_h2b);
    cudaGetSymbolAddress((void**)&as1,  g_as1);
    cudaGetSymbolAddress((void**)&ad1,  g_ad1);
    cudaGetSymbolAddress((void**)&as2,  g_as2);
    cudaGetSymbolAddress((void**)&ad2,  g_ad2);
    cudaGetSymbolAddress((void**)&cnt,  g_cnt);
    cudaGetSymbolAddress((void**)&csr,  g_csr);

    cudaStream_t st = 0;
    const int threads = 256;
    const int eblocks = (E_TOT + threads - 1) / threads;

    cudaMemsetAsync(cnt, 0, N_NODES * sizeof(int), st);
    scatter_kernel<<<eblocks, threads, 0, st>>>(src, dst, cnt, csr);

    // Layer 1
    {
        dim3 grid(HEADS * HF / 64, (N_NODES + 127) / 128);
        gemm_fused_kernel<1, HF><<<grid, 256, 0, st>>>(x, W1, h1b, att_src1, att_dst1,
                                                       as1, ad1, N_NODES, HEADS * HF, IN_F);
        aggregate_kernel<HF, true><<<N_NODES, 256, 0, st>>>(h1b, as1, ad1, cnt, csr, b1, h1m);
    }

    // Layer 2
    {
        dim3 grid(HEADS * OUTF / 64, (N_NODES + 127) / 128);
        gemm_fused_kernel<0, OUTF><<<grid, 256, 0, st>>>(h1m, W2, h2b, att_src2, att_dst2,
                                                         as2, ad2, N_NODES, HEADS * OUTF, HF);
        aggregate_kernel<OUTF, false><<<N_NODES, 256, 0, st>>>(h2b, as2, ad2, cnt, csr, b2, out);
    }
}